// round 3
// baseline (speedup 1.0000x reference)
#include <cuda_runtime.h>
#include <cstdint>
#include <cstddef>

// ---------------- problem constants ----------------
constexpr int N_NODES = 100000;
constexpr int IN_C    = 256;
constexpr int HID_C   = 128;
constexpr int OUT_C   = 64;
constexpr int N_EDGES = 1600000;
constexpr int N_LBL   = 200000;

// ---------------- scratch (device globals; no allocation allowed) ----------
__device__ __align__(16) int   g_deg [N_NODES];
__device__ __align__(16) float g_dinv[N_NODES];
__device__ __align__(16) float g_bufA[(size_t)N_NODES * HID_C]; // h0s, then h (in-place)
__device__ __align__(16) float g_agg [(size_t)N_NODES * HID_C]; // layer-1 scatter accum
__device__ __align__(16) float g_z0s [(size_t)N_NODES * OUT_C]; // (h@W2)*dinv
__device__ __align__(16) float g_agg2[(size_t)N_NODES * OUT_C]; // layer-2 scatter accum
__device__ __align__(16) float g_z   [(size_t)N_NODES * OUT_C]; // final node embeddings

// ---------------- zero scratch accumulators --------------------------------
__global__ void zero_all_kernel() {
    const int idx    = blockIdx.x * blockDim.x + threadIdx.x;
    const int stride = gridDim.x * blockDim.x;
    const float4 z4 = make_float4(0.f, 0.f, 0.f, 0.f);
    const int nA = N_NODES * HID_C / 4;
    float4* a4 = reinterpret_cast<float4*>(g_agg);
    for (int i = idx; i < nA; i += stride) a4[i] = z4;
    const int nB = N_NODES * OUT_C / 4;
    float4* b4 = reinterpret_cast<float4*>(g_agg2);
    for (int i = idx; i < nB; i += stride) b4[i] = z4;
    for (int i = idx; i < N_NODES; i += stride) g_deg[i] = 0;
}

// ---------------- degree (in-degree per dst) --------------------------------
__global__ void deg_count_kernel(const int* __restrict__ ei) {
    const int idx    = blockIdx.x * blockDim.x + threadIdx.x;
    const int stride = gridDim.x * blockDim.x;
    for (int e = idx; e < N_EDGES; e += stride) {
        int d = __ldg(&ei[N_EDGES + e]);
        atomicAdd(&g_deg[d], 1);
    }
}

__global__ void dinv_kernel() {
    const int i = blockIdx.x * blockDim.x + threadIdx.x;
    if (i < N_NODES) {
        // +1 for the self-loop (every node has deg >= 1)
        g_dinv[i] = rsqrtf((float)g_deg[i] + 1.0f);
    }
}

// ---------------- fp32 GEMM with dinv-scaled epilogue -----------------------
// out[r, :] = dinv[r] * (X[r, :] @ W)   ;  X: [N_NODES, K], W: [K, BN]
// BM=128 rows/block, BK=16, 8x8 register tile per thread.
template <int BN, int K>
__device__ __forceinline__ void gemm_scale_core(const float* __restrict__ X,
                                                const float* __restrict__ W,
                                                float* __restrict__ out) {
    constexpr int BM = 128, BK = 16;
    constexpr int TX = BN / 8;      // threads along cols
    constexpr int NT = 16 * TX;     // total threads (rows dim is 16 thread-groups)

    __shared__ float xs[BK][BM];    // transposed X tile
    __shared__ float ws[BK][BN];

    const int tid  = threadIdx.x;
    const int tx   = tid % TX;
    const int ty   = tid / TX;
    const int row0 = blockIdx.x * BM;

    float acc[8][8];
#pragma unroll
    for (int i = 0; i < 8; i++)
#pragma unroll
        for (int j = 0; j < 8; j++) acc[i][j] = 0.f;

    for (int k0 = 0; k0 < K; k0 += BK) {
        // load X tile [BM x BK], store transposed
#pragma unroll
        for (int f = tid; f < BM * BK / 4; f += NT) {
            int r  = f >> 2;        // BK/4 == 4
            int kq = f & 3;
            int gr = row0 + r;
            if (gr > N_NODES - 1) gr = N_NODES - 1;   // clamp (dup row, discarded)
            float4 v = *reinterpret_cast<const float4*>(X + (size_t)gr * K + k0 + kq * 4);
            xs[kq * 4 + 0][r] = v.x;
            xs[kq * 4 + 1][r] = v.y;
            xs[kq * 4 + 2][r] = v.z;
            xs[kq * 4 + 3][r] = v.w;
        }
        // load W tile [BK x BN]
#pragma unroll
        for (int f = tid; f < BK * BN / 4; f += NT) {
            int kr = f / (BN / 4);
            int cq = f % (BN / 4);
            *reinterpret_cast<float4*>(&ws[kr][cq * 4]) =
                *reinterpret_cast<const float4*>(W + (size_t)(k0 + kr) * BN + cq * 4);
        }
        __syncthreads();

#pragma unroll
        for (int kk = 0; kk < BK; kk++) {
            float a[8], b[8];
            *reinterpret_cast<float4*>(a)     = *reinterpret_cast<const float4*>(&xs[kk][ty * 8]);
            *reinterpret_cast<float4*>(a + 4) = *reinterpret_cast<const float4*>(&xs[kk][ty * 8 + 4]);
            *reinterpret_cast<float4*>(b)     = *reinterpret_cast<const float4*>(&ws[kk][tx * 8]);
            *reinterpret_cast<float4*>(b + 4) = *reinterpret_cast<const float4*>(&ws[kk][tx * 8 + 4]);
#pragma unroll
            for (int i = 0; i < 8; i++)
#pragma unroll
                for (int j = 0; j < 8; j++)
                    acc[i][j] = fmaf(a[i], b[j], acc[i][j]);
        }
        __syncthreads();
    }

#pragma unroll
    for (int i = 0; i < 8; i++) {
        int r = row0 + ty * 8 + i;
        if (r < N_NODES) {
            float s = g_dinv[r];
#pragma unroll
            for (int j = 0; j < 8; j += 4) {
                float4 v;
                v.x = acc[i][j + 0] * s;
                v.y = acc[i][j + 1] * s;
                v.z = acc[i][j + 2] * s;
                v.w = acc[i][j + 3] * s;
                *reinterpret_cast<float4*>(out + (size_t)r * BN + tx * 8 + j) = v;
            }
        }
    }
}

__global__ void __launch_bounds__(256) gemm1_kernel(const float* __restrict__ X,
                                                    const float* __restrict__ W) {
    gemm_scale_core<HID_C, IN_C>(X, W, g_bufA);
}
__global__ void __launch_bounds__(128) gemm2_kernel(const float* __restrict__ W) {
    gemm_scale_core<OUT_C, HID_C>(g_bufA, W, g_z0s);
}

// ---------------- scatter: agg[dst] += h0s[src]  (128 feats, 1 warp/edge) ---
__global__ void scatter128_kernel(const int* __restrict__ ei) {
    const int lane = threadIdx.x & 31;
    const int warp = (blockIdx.x * blockDim.x + threadIdx.x) >> 5;
    const int nw   = (gridDim.x * blockDim.x) >> 5;
    for (int e = warp; e < N_EDGES; e += nw) {
        int s = __ldg(&ei[e]);
        int d = __ldg(&ei[N_EDGES + e]);
        float4 v = *reinterpret_cast<const float4*>(&g_bufA[(size_t)s * HID_C + lane * 4]);
        float* dst = &g_agg[(size_t)d * HID_C + lane * 4];
        atomicAdd(dst + 0, v.x);
        atomicAdd(dst + 1, v.y);
        atomicAdd(dst + 2, v.z);
        atomicAdd(dst + 3, v.w);
    }
}

// ---------------- scatter: agg2[dst] += z0s[src]  (64 feats, 16 thr/edge) ---
__global__ void scatter64_kernel(const int* __restrict__ ei) {
    const int t    = blockIdx.x * blockDim.x + threadIdx.x;
    const int l    = t & 15;
    const int sub  = t >> 4;
    const int nsub = (gridDim.x * blockDim.x) >> 4;
    for (int e = sub; e < N_EDGES; e += nsub) {
        int s = __ldg(&ei[e]);
        int d = __ldg(&ei[N_EDGES + e]);
        float4 v = *reinterpret_cast<const float4*>(&g_z0s[(size_t)s * OUT_C + l * 4]);
        float* dst = &g_agg2[(size_t)d * OUT_C + l * 4];
        atomicAdd(dst + 0, v.x);
        atomicAdd(dst + 1, v.y);
        atomicAdd(dst + 2, v.z);
        atomicAdd(dst + 3, v.w);
    }
}

// ---------------- layer epilogues ------------------------------------------
// h = relu(dinv * (agg + h0s) + b1), in-place into g_bufA
__global__ void post1_kernel(const float* __restrict__ b1) {
    const int idx = blockIdx.x * blockDim.x + threadIdx.x;
    const int n4  = N_NODES * HID_C / 4;
    if (idx >= n4) return;
    const int i  = idx / (HID_C / 4);
    const int jq = idx % (HID_C / 4);
    float  s = g_dinv[i];
    float4 a = reinterpret_cast<const float4*>(g_agg)[idx];
    float4 h = reinterpret_cast<const float4*>(g_bufA)[idx];
    float4 b = reinterpret_cast<const float4*>(b1)[jq];
    float4 r;
    r.x = fmaxf(fmaf(s, a.x + h.x, b.x), 0.f);
    r.y = fmaxf(fmaf(s, a.y + h.y, b.y), 0.f);
    r.z = fmaxf(fmaf(s, a.z + h.z, b.z), 0.f);
    r.w = fmaxf(fmaf(s, a.w + h.w, b.w), 0.f);
    reinterpret_cast<float4*>(g_bufA)[idx] = r;
}

// z = dinv * (agg2 + z0s) + b2
__global__ void post2_kernel(const float* __restrict__ b2) {
    const int idx = blockIdx.x * blockDim.x + threadIdx.x;
    const int n4  = N_NODES * OUT_C / 4;
    if (idx >= n4) return;
    const int i  = idx / (OUT_C / 4);
    const int jq = idx % (OUT_C / 4);
    float  s = g_dinv[i];
    float4 a = reinterpret_cast<const float4*>(g_agg2)[idx];
    float4 h = reinterpret_cast<const float4*>(g_z0s)[idx];
    float4 b = reinterpret_cast<const float4*>(b2)[jq];
    float4 r;
    r.x = fmaf(s, a.x + h.x, b.x);
    r.y = fmaf(s, a.y + h.y, b.y);
    r.z = fmaf(s, a.z + h.z, b.z);
    r.w = fmaf(s, a.w + h.w, b.w);
    reinterpret_cast<float4*>(g_z)[idx] = r;
}

// ---------------- final: out[e] = dot(z[src], z[dst]) over 64 dims ----------
__global__ void edge_dot_kernel(const int* __restrict__ eli,
                                float* __restrict__ out) {
    const int lane = threadIdx.x & 31;
    const int warp = (blockIdx.x * blockDim.x + threadIdx.x) >> 5;
    if (warp >= N_LBL) return;
    int s = __ldg(&eli[warp]);
    int d = __ldg(&eli[N_LBL + warp]);
    float2 a = *reinterpret_cast<const float2*>(&g_z[(size_t)s * OUT_C + lane * 2]);
    float2 b = *reinterpret_cast<const float2*>(&g_z[(size_t)d * OUT_C + lane * 2]);
    float p = a.x * b.x + a.y * b.y;
#pragma unroll
    for (int o = 16; o > 0; o >>= 1) p += __shfl_xor_sync(0xffffffffu, p, o);
    if (lane == 0) out[warp] = p;
}

// ---------------- launch ----------------------------------------------------
extern "C" void kernel_launch(void* const* d_in, const int* in_sizes, int n_in,
                              void* d_out, int out_size) {
    const float* x   = (const float*)d_in[0];
    const int*   ei  = (const int*)d_in[1];   // int32! (JAX x64 disabled)
    const int*   eli = (const int*)d_in[2];   // int32!
    const float* W1  = (const float*)d_in[3];
    const float* b1  = (const float*)d_in[4];
    const float* W2  = (const float*)d_in[5];
    const float* b2  = (const float*)d_in[6];
    float*       out = (float*)d_out;

    // 1. zero accumulators + degree
    zero_all_kernel<<<2048, 256>>>();
    // 2. degree + dinv
    deg_count_kernel<<<(N_EDGES + 255) / 256, 256>>>(ei);
    dinv_kernel<<<(N_NODES + 255) / 256, 256>>>();
    // 3. layer 1: h0s = (x@W1)*dinv
    gemm1_kernel<<<(N_NODES + 127) / 128, 256>>>(x, W1);
    // 4. scatter 1: agg[dst] += h0s[src]   (1 warp per edge)
    scatter128_kernel<<<(N_EDGES * 32) / 256, 256>>>(ei);
    // 5. h = relu(dinv*(agg + h0s) + b1)
    post1_kernel<<<(N_NODES * HID_C / 4 + 255) / 256, 256>>>(b1);
    // 6. layer 2: z0s = (h@W2)*dinv
    gemm2_kernel<<<(N_NODES + 127) / 128, 128>>>(W2);
    // 7. scatter 2: agg2[dst] += z0s[src]  (16 threads per edge)
    scatter64_kernel<<<(N_EDGES * 16) / 256, 256>>>(ei);
    // 8. z = dinv*(agg2 + z0s) + b2
    post2_kernel<<<(N_NODES * OUT_C / 4 + 255) / 256, 256>>>(b2);
    // 9. label-edge dot products
    edge_dot_kernel<<<(N_LBL * 32 + 255) / 256, 256>>>(eli, out);
}

// round 5
// speedup vs baseline: 1.7407x; 1.7407x over previous
#include <cuda_runtime.h>
#include <cstdint>
#include <cstddef>

// ---------------- problem constants ----------------
constexpr int N_NODES = 100000;
constexpr int IN_C    = 256;
constexpr int HID_C   = 128;
constexpr int OUT_C   = 64;
constexpr int N_EDGES = 1600000;
constexpr int N_LBL   = 200000;

// ---------------- scratch (device globals) ----------------------------------
__device__ __align__(16) int   g_deg   [N_NODES];
__device__ __align__(16) int   g_rowptr[N_NODES + 1];
__device__ __align__(16) int   g_cursor[N_NODES];
__device__ __align__(16) int   g_col   [N_EDGES];
__device__ __align__(16) float g_dinv  [N_NODES];
__device__ __align__(16) float g_bufA[(size_t)N_NODES * HID_C]; // h0s = (x@W1)*dinv
__device__ __align__(16) float g_h   [(size_t)N_NODES * HID_C]; // h (post layer 1)
__device__ __align__(16) float g_z0s [(size_t)N_NODES * OUT_C]; // (h@W2)*dinv
__device__ __align__(16) float g_z   [(size_t)N_NODES * OUT_C]; // final node embeddings

// ---------------- degree -----------------------------------------------------
__global__ void zero_deg_kernel() {
    const int i = blockIdx.x * blockDim.x + threadIdx.x;
    if (i < N_NODES) g_deg[i] = 0;
}

__global__ void deg_count_kernel(const int* __restrict__ ei) {
    const int idx    = blockIdx.x * blockDim.x + threadIdx.x;
    const int stride = gridDim.x * blockDim.x;
    for (int e = idx; e < N_EDGES; e += stride)
        atomicAdd(&g_deg[__ldg(&ei[N_EDGES + e])], 1);
}

// ---------------- rowptr = exclusive scan of deg; cursor = copy --------------
constexpr int SCAN_T  = 1024;
constexpr int SCAN_CH = (N_NODES + SCAN_T - 1) / SCAN_T;   // 98

__global__ void rowptr_kernel() {
    __shared__ int part[SCAN_T];
    const int t    = threadIdx.x;
    const int base = t * SCAN_CH;
    int sum = 0;
    for (int i = 0; i < SCAN_CH; i++) {
        int idx = base + i;
        if (idx < N_NODES) sum += g_deg[idx];
    }
    part[t] = sum;
    __syncthreads();
#pragma unroll
    for (int off = 1; off < SCAN_T; off <<= 1) {
        int v = (t >= off) ? part[t - off] : 0;
        __syncthreads();
        part[t] += v;
        __syncthreads();
    }
    int run = part[t] - sum;   // exclusive prefix for this chunk
    for (int i = 0; i < SCAN_CH; i++) {
        int idx = base + i;
        if (idx < N_NODES) {
            g_rowptr[idx] = run;
            g_cursor[idx] = run;
            run += g_deg[idx];
        }
    }
    if (t == 0) g_rowptr[N_NODES] = part[SCAN_T - 1];
}

// ---------------- CSR fill: col[pos] = src, grouped by dst -------------------
__global__ void fill_kernel(const int* __restrict__ ei) {
    const int idx    = blockIdx.x * blockDim.x + threadIdx.x;
    const int stride = gridDim.x * blockDim.x;
    for (int e = idx; e < N_EDGES; e += stride) {
        int s = __ldg(&ei[e]);
        int d = __ldg(&ei[N_EDGES + e]);
        int pos = atomicAdd(&g_cursor[d], 1);
        g_col[pos] = s;
    }
}

__global__ void dinv_kernel() {
    const int i = blockIdx.x * blockDim.x + threadIdx.x;
    if (i < N_NODES) g_dinv[i] = rsqrtf((float)g_deg[i] + 1.0f);  // +1 self-loop
}

// ---------------- fp32 GEMM with dinv-scaled epilogue -----------------------
// out[r, :] = dinv[r] * (X[r, :] @ W)
template <int BN, int K>
__device__ __forceinline__ void gemm_scale_core(const float* __restrict__ X,
                                                const float* __restrict__ W,
                                                float* __restrict__ out) {
    constexpr int BM = 128, BK = 16;
    constexpr int TX = BN / 8;
    constexpr int NT = 16 * TX;

    __shared__ float xs[BK][BM];
    __shared__ float ws[BK][BN];

    const int tid  = threadIdx.x;
    const int tx   = tid % TX;
    const int ty   = tid / TX;
    const int row0 = blockIdx.x * BM;

    float acc[8][8];
#pragma unroll
    for (int i = 0; i < 8; i++)
#pragma unroll
        for (int j = 0; j < 8; j++) acc[i][j] = 0.f;

    for (int k0 = 0; k0 < K; k0 += BK) {
#pragma unroll
        for (int f = tid; f < BM * BK / 4; f += NT) {
            int r  = f >> 2;
            int kq = f & 3;
            int gr = row0 + r;
            if (gr > N_NODES - 1) gr = N_NODES - 1;
            float4 v = *reinterpret_cast<const float4*>(X + (size_t)gr * K + k0 + kq * 4);
            xs[kq * 4 + 0][r] = v.x;
            xs[kq * 4 + 1][r] = v.y;
            xs[kq * 4 + 2][r] = v.z;
            xs[kq * 4 + 3][r] = v.w;
        }
#pragma unroll
        for (int f = tid; f < BK * BN / 4; f += NT) {
            int kr = f / (BN / 4);
            int cq = f % (BN / 4);
            *reinterpret_cast<float4*>(&ws[kr][cq * 4]) =
                *reinterpret_cast<const float4*>(W + (size_t)(k0 + kr) * BN + cq * 4);
        }
        __syncthreads();

#pragma unroll
        for (int kk = 0; kk < BK; kk++) {
            float a[8], b[8];
            *reinterpret_cast<float4*>(a)     = *reinterpret_cast<const float4*>(&xs[kk][ty * 8]);
            *reinterpret_cast<float4*>(a + 4) = *reinterpret_cast<const float4*>(&xs[kk][ty * 8 + 4]);
            *reinterpret_cast<float4*>(b)     = *reinterpret_cast<const float4*>(&ws[kk][tx * 8]);
            *reinterpret_cast<float4*>(b + 4) = *reinterpret_cast<const float4*>(&ws[kk][tx * 8 + 4]);
#pragma unroll
            for (int i = 0; i < 8; i++)
#pragma unroll
                for (int j = 0; j < 8; j++)
                    acc[i][j] = fmaf(a[i], b[j], acc[i][j]);
        }
        __syncthreads();
    }

#pragma unroll
    for (int i = 0; i < 8; i++) {
        int r = row0 + ty * 8 + i;
        if (r < N_NODES) {
            float s = g_dinv[r];
#pragma unroll
            for (int j = 0; j < 8; j += 4) {
                float4 v;
                v.x = acc[i][j + 0] * s;
                v.y = acc[i][j + 1] * s;
                v.z = acc[i][j + 2] * s;
                v.w = acc[i][j + 3] * s;
                *reinterpret_cast<float4*>(out + (size_t)r * BN + tx * 8 + j) = v;
            }
        }
    }
}

__global__ void __launch_bounds__(256) gemm1_kernel(const float* __restrict__ X,
                                                    const float* __restrict__ W) {
    gemm_scale_core<HID_C, IN_C>(X, W, g_bufA);
}
__global__ void __launch_bounds__(128) gemm2_kernel(const float* __restrict__ W) {
    gemm_scale_core<OUT_C, HID_C>(g_h, W, g_z0s);
}

// ---------------- CSR aggregation, layer 1 (128 feats, warp/node) -----------
// h[i] = relu(dinv[i] * (h0s[i] + sum_{s in N(i)} h0s[s]) + b1)
__global__ void __launch_bounds__(256) agg128_kernel(const float* __restrict__ b1) {
    const int lane = threadIdx.x & 31;
    const int node = (blockIdx.x * blockDim.x + threadIdx.x) >> 5;
    if (node >= N_NODES) return;
    const int beg = g_rowptr[node];
    const int end = g_rowptr[node + 1];
    const float4* __restrict__ H = reinterpret_cast<const float4*>(g_bufA);

    float4 acc = H[(size_t)node * 32 + lane];   // self-loop term
    int j = beg;
    for (; j + 3 < end; j += 4) {
        int s0 = __ldg(&g_col[j + 0]);
        int s1 = __ldg(&g_col[j + 1]);
        int s2 = __ldg(&g_col[j + 2]);
        int s3 = __ldg(&g_col[j + 3]);
        float4 v0 = H[(size_t)s0 * 32 + lane];
        float4 v1 = H[(size_t)s1 * 32 + lane];
        float4 v2 = H[(size_t)s2 * 32 + lane];
        float4 v3 = H[(size_t)s3 * 32 + lane];
        acc.x += (v0.x + v1.x) + (v2.x + v3.x);
        acc.y += (v0.y + v1.y) + (v2.y + v3.y);
        acc.z += (v0.z + v1.z) + (v2.z + v3.z);
        acc.w += (v0.w + v1.w) + (v2.w + v3.w);
    }
    for (; j < end; j++) {
        int s = __ldg(&g_col[j]);
        float4 v = H[(size_t)s * 32 + lane];
        acc.x += v.x; acc.y += v.y; acc.z += v.z; acc.w += v.w;
    }
    const float sc = g_dinv[node];
    const float4 b = reinterpret_cast<const float4*>(b1)[lane];
    float4 r;
    r.x = fmaxf(fmaf(sc, acc.x, b.x), 0.f);
    r.y = fmaxf(fmaf(sc, acc.y, b.y), 0.f);
    r.z = fmaxf(fmaf(sc, acc.z, b.z), 0.f);
    r.w = fmaxf(fmaf(sc, acc.w, b.w), 0.f);
    reinterpret_cast<float4*>(g_h)[(size_t)node * 32 + lane] = r;
}

// ---------------- CSR aggregation, layer 2 (64 feats, 16 threads/node) ------
// z[i] = dinv[i] * (z0s[i] + sum z0s[s]) + b2
__global__ void __launch_bounds__(256) agg64_kernel(const float* __restrict__ b2) {
    const int t    = blockIdx.x * blockDim.x + threadIdx.x;
    const int l    = t & 15;
    const int node = t >> 4;
    if (node >= N_NODES) return;
    const int beg = g_rowptr[node];
    const int end = g_rowptr[node + 1];
    const float4* __restrict__ Z = reinterpret_cast<const float4*>(g_z0s);

    float4 acc = Z[(size_t)node * 16 + l];
    int j = beg;
    for (; j + 3 < end; j += 4) {
        int s0 = __ldg(&g_col[j + 0]);
        int s1 = __ldg(&g_col[j + 1]);
        int s2 = __ldg(&g_col[j + 2]);
        int s3 = __ldg(&g_col[j + 3]);
        float4 v0 = Z[(size_t)s0 * 16 + l];
        float4 v1 = Z[(size_t)s1 * 16 + l];
        float4 v2 = Z[(size_t)s2 * 16 + l];
        float4 v3 = Z[(size_t)s3 * 16 + l];
        acc.x += (v0.x + v1.x) + (v2.x + v3.x);
        acc.y += (v0.y + v1.y) + (v2.y + v3.y);
        acc.z += (v0.z + v1.z) + (v2.z + v3.z);
        acc.w += (v0.w + v1.w) + (v2.w + v3.w);
    }
    for (; j < end; j++) {
        int s = __ldg(&g_col[j]);
        float4 v = Z[(size_t)s * 16 + l];
        acc.x += v.x; acc.y += v.y; acc.z += v.z; acc.w += v.w;
    }
    const float sc = g_dinv[node];
    const float4 b = reinterpret_cast<const float4*>(b2)[l];
    float4 r;
    r.x = fmaf(sc, acc.x, b.x);
    r.y = fmaf(sc, acc.y, b.y);
    r.z = fmaf(sc, acc.z, b.z);
    r.w = fmaf(sc, acc.w, b.w);
    reinterpret_cast<float4*>(g_z)[(size_t)node * 16 + l] = r;
}

// ---------------- final: out[e] = dot(z[src], z[dst]) over 64 dims ----------
__global__ void edge_dot_kernel(const int* __restrict__ eli,
                                float* __restrict__ out) {
    const int lane = threadIdx.x & 31;
    const int warp = (blockIdx.x * blockDim.x + threadIdx.x) >> 5;
    if (warp >= N_LBL) return;
    int s = __ldg(&eli[warp]);
    int d = __ldg(&eli[N_LBL + warp]);
    float2 a = *reinterpret_cast<const float2*>(&g_z[(size_t)s * OUT_C + lane * 2]);
    float2 b = *reinterpret_cast<const float2*>(&g_z[(size_t)d * OUT_C + lane * 2]);
    float p = a.x * b.x + a.y * b.y;
#pragma unroll
    for (int o = 16; o > 0; o >>= 1) p += __shfl_xor_sync(0xffffffffu, p, o);
    if (lane == 0) out[warp] = p;
}

// ---------------- launch ----------------------------------------------------
extern "C" void kernel_launch(void* const* d_in, const int* in_sizes, int n_in,
                              void* d_out, int out_size) {
    const float* x   = (const float*)d_in[0];
    const int*   ei  = (const int*)d_in[1];   // int32 (JAX x64 disabled)
    const int*   eli = (const int*)d_in[2];
    const float* W1  = (const float*)d_in[3];
    const float* b1  = (const float*)d_in[4];
    const float* W2  = (const float*)d_in[5];
    const float* b2  = (const float*)d_in[6];
    float*       out = (float*)d_out;

    // CSR build
    zero_deg_kernel<<<(N_NODES + 255) / 256, 256>>>();
    deg_count_kernel<<<2048, 256>>>(ei);
    rowptr_kernel<<<1, SCAN_T>>>();
    fill_kernel<<<2048, 256>>>(ei);
    dinv_kernel<<<(N_NODES + 255) / 256, 256>>>();
    // layer 1
    gemm1_kernel<<<(N_NODES + 127) / 128, 256>>>(x, W1);
    agg128_kernel<<<(N_NODES * 32 + 255) / 256, 256>>>(b1);
    // layer 2
    gemm2_kernel<<<(N_NODES + 127) / 128, 128>>>(W2);
    agg64_kernel<<<(N_NODES * 16 + 255) / 256, 256>>>(b2);
    // label-edge dot products
    edge_dot_kernel<<<(N_LBL * 32 + 255) / 256, 256>>>(eli, out);
}